// round 8
// baseline (speedup 1.0000x reference)
#include <cuda_runtime.h>

// TypeAttention reduces algebraically to alpha[e] = 1 / in_degree(dst[e]) per
// relation (per-dst softmax over identical logits = uniform). Output = concat.
//
// Fork-join graph:
//   s0: hist_ui -> gather_ui -> memset(cnt_ui) ------\
//   s1:   (after hist_ui) hist_iu -> gather_iu -> memset(cnt_iu) -> join
// gather_ui overlaps hist_iu; memset_ui overlaps gather_iu. 8 edges/thread in
// both kernels for memory-level parallelism (gather is latency-exposed).
// Counts re-zeroed each replay; static zero-init covers call #1.

#define MAX_NODES 100000
#define TPB 256

__device__ int g_cnt[2 * MAX_NODES];   // [0,N): ui  [N,2N): iu

__global__ void hist1_kernel(const int* __restrict__ dst, int* __restrict__ cnt,
                             int E) {
    int i = blockIdx.x * TPB + threadIdx.x;
    int e8 = E >> 3;
    if (i < e8) {
        int4 a = __ldg((const int4*)dst + 2 * i);
        int4 b = __ldg((const int4*)dst + 2 * i + 1);
        atomicAdd(&cnt[a.x], 1);
        atomicAdd(&cnt[a.y], 1);
        atomicAdd(&cnt[a.z], 1);
        atomicAdd(&cnt[a.w], 1);
        atomicAdd(&cnt[b.x], 1);
        atomicAdd(&cnt[b.y], 1);
        atomicAdd(&cnt[b.z], 1);
        atomicAdd(&cnt[b.w], 1);
    } else if (i == e8) {
        for (int j = e8 << 3; j < E; j++) atomicAdd(&cnt[dst[j]], 1);
    }
}

__global__ void gather1_kernel(const int* __restrict__ dst,
                               const int* __restrict__ cnt,
                               float* __restrict__ out, int E) {
    int i = blockIdx.x * TPB + threadIdx.x;
    int e8 = E >> 3;
    if (i < e8) {
        int4 a = __ldg((const int4*)dst + 2 * i);
        int4 b = __ldg((const int4*)dst + 2 * i + 1);
        // 8 independent random loads in flight before any use
        int c0 = cnt[a.x], c1 = cnt[a.y], c2 = cnt[a.z], c3 = cnt[a.w];
        int c4 = cnt[b.x], c5 = cnt[b.y], c6 = cnt[b.z], c7 = cnt[b.w];
        float4 r0, r1;
        r0.x = 1.0f / (float)c0;
        r0.y = 1.0f / (float)c1;
        r0.z = 1.0f / (float)c2;
        r0.w = 1.0f / (float)c3;
        r1.x = 1.0f / (float)c4;
        r1.y = 1.0f / (float)c5;
        r1.z = 1.0f / (float)c6;
        r1.w = 1.0f / (float)c7;
        ((float4*)out)[2 * i]     = r0;
        ((float4*)out)[2 * i + 1] = r1;
    } else if (i == e8) {
        for (int j = e8 << 3; j < E; j++) out[j] = 1.0f / (float)cnt[dst[j]];
    }
}

extern "C" void kernel_launch(void* const* d_in, const int* in_sizes, int n_in,
                              void* d_out, int out_size) {
    // Inputs: h_user, h_item, Wl_user, bl_user, Wl_item, bl_item,
    //         Wr_user, br_user, Wr_item, br_item, attn_w,
    //         src_ui, dst_ui, src_iu, dst_iu
    const int* dst_ui = (const int*)d_in[12];
    const int* dst_iu = (const int*)d_in[14];
    float* out = (float*)d_out;
    int E = in_sizes[12];

    static cudaStream_t s1 = nullptr;
    static cudaEvent_t ev_fork = nullptr, ev_join = nullptr;
    static int* p_cnt = nullptr;
    if (!s1) {
        cudaStreamCreateWithFlags(&s1, cudaStreamNonBlocking);
        cudaEventCreateWithFlags(&ev_fork, cudaEventDisableTiming);
        cudaEventCreateWithFlags(&ev_join, cudaEventDisableTiming);
        cudaGetSymbolAddress((void**)&p_cnt, g_cnt);
    }

    int e8_threads = (E >> 3) + 1;   // +1 thread for the tail
    int eb = (e8_threads + TPB - 1) / TPB;

    int* cnt_ui = p_cnt;
    int* cnt_iu = p_cnt + MAX_NODES;

    // s0: hist_ui
    hist1_kernel<<<eb, TPB>>>(dst_ui, cnt_ui, E);
    cudaEventRecord(ev_fork, 0);

    // s1: hist_iu starts after hist_ui (overlaps gather_ui on s0)
    cudaStreamWaitEvent(s1, ev_fork, 0);
    hist1_kernel<<<eb, TPB, 0, s1>>>(dst_iu, cnt_iu, E);

    // s0: gather_ui, then clean ui counts (overlaps s1's gather_iu)
    gather1_kernel<<<eb, TPB>>>(dst_ui, cnt_ui, out, E);
    cudaMemsetAsync(cnt_ui, 0, sizeof(int) * MAX_NODES);

    // s1: gather_iu, clean iu counts, join back to s0
    gather1_kernel<<<eb, TPB, 0, s1>>>(dst_iu, cnt_iu, out + E, E);
    cudaMemsetAsync(cnt_iu, 0, sizeof(int) * MAX_NODES, s1);
    cudaEventRecord(ev_join, s1);
    cudaStreamWaitEvent(0, ev_join, 0);
}

// round 9
// speedup vs baseline: 1.1402x; 1.1402x over previous
#include <cuda_runtime.h>

// TypeAttention reduces algebraically to alpha[e] = 1 / in_degree(dst[e]) per
// relation (per-dst softmax over identical logits = uniform). Output = concat.
//
// Diagonal 3-kernel pipeline on ONE stream, self-cleaning, no memsets:
//   k1: hist_ui (REDs)            + zero cnt_iu
//   k2: gather_ui (L1tex-bound)   + hist_iu (L2-atomic-bound)  <- pipe overlap
//   k3: gather_iu                 + zero cnt_ui (for next replay)
// Static zero-init covers the first call; each replay re-zeros both tables.

#define MAX_NODES 100000
#define TPB 256

__device__ int g_cnt[2 * MAX_NODES];   // [0,N): ui  [N,2N): iu

// k1: histogram relation ui; also zero cnt_iu (dead until k2's REDs).
__global__ void k1_hist_ui_zero_iu(const int* __restrict__ dst_ui, int E, int Nn) {
    int i = blockIdx.x * TPB + threadIdx.x;
    int e4 = E >> 2;
    if (i < e4) {
        int4 a = __ldg((const int4*)dst_ui + i);
        atomicAdd(&g_cnt[a.x], 1);
        atomicAdd(&g_cnt[a.y], 1);
        atomicAdd(&g_cnt[a.z], 1);
        atomicAdd(&g_cnt[a.w], 1);
    } else if (i == e4) {
        for (int j = e4 << 2; j < E; j++) atomicAdd(&g_cnt[dst_ui[j]], 1);
    }
    if (i < Nn) g_cnt[MAX_NODES + i] = 0;   // Nn <= e4-range threads exist (E/4 >> Nn/? ok: 250K threads > 100K)
}

// k2: gather relation ui (reads final cnt_ui) + histogram relation iu.
__global__ void k2_gather_ui_hist_iu(const int* __restrict__ dst_ui,
                                     const int* __restrict__ dst_iu,
                                     float* __restrict__ out, int E) {
    int i = blockIdx.x * TPB + threadIdx.x;
    int e4 = E >> 2;
    if (i < e4) {
        int4 a = __ldg((const int4*)dst_ui + i);
        int4 b = __ldg((const int4*)dst_iu + i);
        // REDs are fire-and-forget: issue first, they drain under the gather.
        atomicAdd(&g_cnt[MAX_NODES + b.x], 1);
        atomicAdd(&g_cnt[MAX_NODES + b.y], 1);
        atomicAdd(&g_cnt[MAX_NODES + b.z], 1);
        atomicAdd(&g_cnt[MAX_NODES + b.w], 1);
        float4 r;
        r.x = 1.0f / (float)g_cnt[a.x];
        r.y = 1.0f / (float)g_cnt[a.y];
        r.z = 1.0f / (float)g_cnt[a.z];
        r.w = 1.0f / (float)g_cnt[a.w];
        ((float4*)out)[i] = r;
    } else if (i == e4) {
        for (int j = e4 << 2; j < E; j++) {
            atomicAdd(&g_cnt[MAX_NODES + dst_iu[j]], 1);
            out[j] = 1.0f / (float)g_cnt[dst_ui[j]];
        }
    }
}

// k3: gather relation iu; also zero cnt_ui for the next graph replay.
__global__ void k3_gather_iu_zero_ui(const int* __restrict__ dst_iu,
                                     float* __restrict__ out_iu, int E, int Nn) {
    int i = blockIdx.x * TPB + threadIdx.x;
    int e4 = E >> 2;
    if (i < e4) {
        int4 b = __ldg((const int4*)dst_iu + i);
        float4 r;
        r.x = 1.0f / (float)g_cnt[MAX_NODES + b.x];
        r.y = 1.0f / (float)g_cnt[MAX_NODES + b.y];
        r.z = 1.0f / (float)g_cnt[MAX_NODES + b.z];
        r.w = 1.0f / (float)g_cnt[MAX_NODES + b.w];
        ((float4*)out_iu)[i] = r;
    } else if (i == e4) {
        for (int j = e4 << 2; j < E; j++)
            out_iu[j] = 1.0f / (float)g_cnt[MAX_NODES + dst_iu[j]];
    }
    if (i < Nn) g_cnt[i] = 0;
}

extern "C" void kernel_launch(void* const* d_in, const int* in_sizes, int n_in,
                              void* d_out, int out_size) {
    // Inputs: h_user, h_item, Wl_user, bl_user, Wl_item, bl_item,
    //         Wr_user, br_user, Wr_item, br_item, attn_w,
    //         src_ui, dst_ui, src_iu, dst_iu
    const int* dst_ui = (const int*)d_in[12];
    const int* dst_iu = (const int*)d_in[14];
    float* out = (float*)d_out;

    int D  = in_sizes[3];
    int Nn = in_sizes[0] / D;
    if (Nn > MAX_NODES) Nn = MAX_NODES;
    int E = in_sizes[12];

    int e4_threads = (E >> 2) + 1;                 // +1 thread for the tail
    int nthreads = e4_threads > Nn ? e4_threads : Nn;  // cover the zeroing too
    int eb = (nthreads + TPB - 1) / TPB;

    k1_hist_ui_zero_iu<<<eb, TPB>>>(dst_ui, E, Nn);
    k2_gather_ui_hist_iu<<<eb, TPB>>>(dst_ui, dst_iu, out, E);
    k3_gather_iu_zero_ui<<<eb, TPB>>>(dst_iu, out + E, E, Nn);
}